// round 1
// baseline (speedup 1.0000x reference)
#include <cuda_runtime.h>
#include <math.h>

// ---------------------------------------------------------------------------
// PairwiseInteractionHead: B=4, LL=LP=256, D=256, H=128, TOPK=100
// Factorization: z1[h] = A1[i,h] + B1[j,h] + sum_k Wc[h,k] l[i,k] p[j,k]
//                               + sum_k Wd[h,k] |l[i,k]-p[j,k]|
// where A1 = l_proj @ W1[:,0:256]^T + b1, B1 = p_proj @ W1[:,256:512]^T.
// ---------------------------------------------------------------------------

#define NB 4
#define LSEQ 256
#define DDIM 256
#define HDIM 128
#define NPAIR_B 65536      // 256*256
#define TOPK_K 100

// scratch (device globals: no allocations allowed)
__device__ float g_lproj[NB * LSEQ * DDIM];
__device__ float g_pproj[NB * LSEQ * DDIM];
__device__ float g_A1[NB * LSEQ * HDIM];
__device__ float g_B1[NB * LSEQ * HDIM];
__device__ int   g_lmask[NB * LSEQ];
__device__ int   g_pmask[NB * LSEQ];
__device__ int   g_flags[2];

__device__ __forceinline__ float gelu_f(float x) {
    return 0.5f * x * (1.0f + erff(x * 0.70710678118654752440f));
}

// ---------------------------------------------------------------------------
// Pad-dtype detection: bool arrays may arrive as uint8 (1B), int32 or float32.
// Scan the first 1024 bytes (safe lower bound for all candidates) and classify
// deterministically.  flag: 0=all-zero, 1=uint8, 2=float32, 3=int32
// ---------------------------------------------------------------------------
__global__ void detect_kernel(const unsigned char* lp, const unsigned char* pp) {
    __shared__ int s_nonbin, s_oddnz, s_anynz;
    const unsigned char* p = blockIdx.x ? pp : lp;
    if (threadIdx.x == 0) { s_nonbin = 0; s_oddnz = 0; s_anynz = 0; }
    __syncthreads();
    int nonbin = 0, oddnz = 0, anynz = 0;
    for (int i = threadIdx.x; i < 1024; i += blockDim.x) {
        unsigned v = p[i];
        if (v) { anynz = 1; if (v > 1u) nonbin = 1; if (i & 3) oddnz = 1; }
    }
    if (nonbin) atomicOr(&s_nonbin, 1);
    if (oddnz)  atomicOr(&s_oddnz, 1);
    if (anynz)  atomicOr(&s_anynz, 1);
    __syncthreads();
    if (threadIdx.x == 0) {
        int f;
        if (!s_anynz) f = 0;
        else if (s_nonbin) f = 2;   // bytes outside {0,1} -> float32 pattern
        else if (s_oddnz) f = 1;    // ones at non-word-aligned bytes -> uint8
        else f = 3;                 // ones only at word starts -> int32
        g_flags[blockIdx.x] = f;
    }
}

__global__ void mask_kernel(const void* lp, const void* pp) {
    int buf = blockIdx.x;
    const void* p = buf ? pp : lp;
    int f = g_flags[buf];
    int i = threadIdx.x;   // 1024 threads == NB*LSEQ
    int m;
    if (f == 0) m = 0;
    else if (f == 1) m = (((const unsigned char*)p)[i] != 0);
    else if (f == 2) m = (((const float*)p)[i] != 0.0f);
    else m = (((const int*)p)[i] != 0);
    (buf ? g_pmask : g_lmask)[i] = m;
}

// ---------------------------------------------------------------------------
// Projection GEMM: rows [0,1024) -> l_proj = l_tok @ Wl^T + bl
//                  rows [1024,2048) -> p_proj = p_tok @ Wp^T + bp
// M=2048 N=256 K=256. 64x64 tile, 256 threads, 4x4 micro.
// ---------------------------------------------------------------------------
__global__ __launch_bounds__(256) void proj_kernel(
    const float* __restrict__ ltok, const float* __restrict__ ptok,
    const float* __restrict__ Wl, const float* __restrict__ bl,
    const float* __restrict__ Wp, const float* __restrict__ bp)
{
    __shared__ float As[16][68];
    __shared__ float Bs[16][68];
    const int n0 = blockIdx.x * 64;
    const int m0 = blockIdx.y * 64;
    const bool isP = (m0 >= 1024);
    const float* in   = isP ? ptok : ltok;
    const float* W    = isP ? Wp : Wl;
    const float* bias = isP ? bp : bl;
    const int mb = isP ? (m0 - 1024) : m0;
    float* outp = isP ? g_pproj : g_lproj;
    const int tid = threadIdx.x;
    const int tx = tid & 15, ty = tid >> 4;
    const int lr = tid >> 2, lc = (tid & 3) * 4;
    float acc[4][4] = {};
    for (int kt = 0; kt < 256; kt += 16) {
        float4 a4 = *(const float4*)&in[(mb + lr) * 256 + kt + lc];
        float4 b4 = *(const float4*)&W[(n0 + lr) * 256 + kt + lc];
        As[lc + 0][lr] = a4.x; As[lc + 1][lr] = a4.y; As[lc + 2][lr] = a4.z; As[lc + 3][lr] = a4.w;
        Bs[lc + 0][lr] = b4.x; Bs[lc + 1][lr] = b4.y; Bs[lc + 2][lr] = b4.z; Bs[lc + 3][lr] = b4.w;
        __syncthreads();
#pragma unroll
        for (int e = 0; e < 16; e++) {
            float4 av = *(const float4*)&As[e][ty * 4];
            float4 bv = *(const float4*)&Bs[e][tx * 4];
            acc[0][0] += av.x * bv.x; acc[0][1] += av.x * bv.y; acc[0][2] += av.x * bv.z; acc[0][3] += av.x * bv.w;
            acc[1][0] += av.y * bv.x; acc[1][1] += av.y * bv.y; acc[1][2] += av.y * bv.z; acc[1][3] += av.y * bv.w;
            acc[2][0] += av.z * bv.x; acc[2][1] += av.z * bv.y; acc[2][2] += av.z * bv.z; acc[2][3] += av.z * bv.w;
            acc[3][0] += av.w * bv.x; acc[3][1] += av.w * bv.y; acc[3][2] += av.w * bv.z; acc[3][3] += av.w * bv.w;
        }
        __syncthreads();
    }
#pragma unroll
    for (int ii = 0; ii < 4; ii++) {
#pragma unroll
        for (int jj = 0; jj < 4; jj++) {
            int n = n0 + tx * 4 + jj;
            outp[(mb + ty * 4 + ii) * 256 + n] = acc[ii][jj] + bias[n];
        }
    }
}

// ---------------------------------------------------------------------------
// A1 = l_proj @ W1[:,0:256]^T + b1 ; B1 = p_proj @ W1[:,256:512]^T
// M=2048 N=128 K=256.
// ---------------------------------------------------------------------------
__global__ __launch_bounds__(256) void a1b1_kernel(
    const float* __restrict__ W1, const float* __restrict__ b1)
{
    __shared__ float As[16][68];
    __shared__ float Bs[16][68];
    const int n0 = blockIdx.x * 64;
    const int m0 = blockIdx.y * 64;
    const bool isP = (m0 >= 1024);
    const float* in = isP ? g_pproj : g_lproj;
    const int mb = isP ? (m0 - 1024) : m0;
    const int colOff = isP ? 256 : 0;
    float* outp = isP ? g_B1 : g_A1;
    const int tid = threadIdx.x;
    const int tx = tid & 15, ty = tid >> 4;
    const int lr = tid >> 2, lc = (tid & 3) * 4;
    float acc[4][4] = {};
    for (int kt = 0; kt < 256; kt += 16) {
        float4 a4 = *(const float4*)&in[(mb + lr) * 256 + kt + lc];
        float4 b4 = *(const float4*)&W1[(n0 + lr) * 1024 + colOff + kt + lc];
        As[lc + 0][lr] = a4.x; As[lc + 1][lr] = a4.y; As[lc + 2][lr] = a4.z; As[lc + 3][lr] = a4.w;
        Bs[lc + 0][lr] = b4.x; Bs[lc + 1][lr] = b4.y; Bs[lc + 2][lr] = b4.z; Bs[lc + 3][lr] = b4.w;
        __syncthreads();
#pragma unroll
        for (int e = 0; e < 16; e++) {
            float4 av = *(const float4*)&As[e][ty * 4];
            float4 bv = *(const float4*)&Bs[e][tx * 4];
            acc[0][0] += av.x * bv.x; acc[0][1] += av.x * bv.y; acc[0][2] += av.x * bv.z; acc[0][3] += av.x * bv.w;
            acc[1][0] += av.y * bv.x; acc[1][1] += av.y * bv.y; acc[1][2] += av.y * bv.z; acc[1][3] += av.y * bv.w;
            acc[2][0] += av.z * bv.x; acc[2][1] += av.z * bv.y; acc[2][2] += av.z * bv.z; acc[2][3] += av.z * bv.w;
            acc[3][0] += av.w * bv.x; acc[3][1] += av.w * bv.y; acc[3][2] += av.w * bv.z; acc[3][3] += av.w * bv.w;
        }
        __syncthreads();
    }
#pragma unroll
    for (int ii = 0; ii < 4; ii++) {
#pragma unroll
        for (int jj = 0; jj < 4; jj++) {
            int n = n0 + tx * 4 + jj;
            float bv = isP ? 0.0f : b1[n];
            outp[(mb + ty * 4 + ii) * 128 + n] = acc[ii][jj] + bv;
        }
    }
}

// ---------------------------------------------------------------------------
// Main pair kernel. Block = (b, 16 i's, 16 j's) = 256 pairs, 512 threads.
// GEMM1 K=512 (on-the-fly X = [l*p ; |l-p|]), gelu, GEMM2 K=128, gelu, w3 dot.
// Thread micro-tile: 8 pairs x 8 h (64 fp32 accumulators).
// Dynamic smem = 204800 B (phase2 Yt[128][264] + W2s[128][136] alias phase1).
// ---------------------------------------------------------------------------
__global__ __launch_bounds__(512, 1) void pair_kernel(
    const float* __restrict__ W1, const float* __restrict__ W2,
    const float* __restrict__ W3, const float* __restrict__ b2g,
    const float* __restrict__ b3, float* __restrict__ out)
{
    extern __shared__ float sm[];
    // phase 1 layout (floats)
    float* Ls  = sm;                    // [16][260]
    float* Ps  = sm + 16 * 260;         // [16][260]
    float* Xs  = sm + 2 * 16 * 260;     // [32][256]
    float* Wks = Xs + 32 * 256;         // [32][136]
    float* A1s = Wks + 32 * 136;        // [16][132]
    float* B1s = A1s + 16 * 132;        // [16][132]   (ends at 25088 floats)
    // phase 2 (aliased; ordering guarded by __syncthreads)
    float* Yt  = sm;                    // [128][264]  (33792 floats)
    float* W2s = sm + 128 * 264;        // [128][136]  (total 51200 floats = 204800 B)

    const int tid = threadIdx.x;
    const int b  = blockIdx.z;
    const int it = blockIdx.y * 16;
    const int jt = blockIdx.x * 16;
    const int pg = tid >> 4;        // 0..31 pair group (8 pairs)
    const int hg = tid & 15;        // 0..15 h group (8 h)
    const int p0 = pg * 8;
    const int h0 = hg * 8;
    const int my_i = p0 >> 4;       // all 8 pairs of this thread share one i
    const int j0 = p0 & 15;         // 0 or 8

    // ---- initial loads ----
    {
        const float* lsrc = g_lproj + (b * 256 + it) * 256;
        const float* psrc = g_pproj + (b * 256 + jt) * 256;
#pragma unroll
        for (int q = 0; q < 2; q++) {
            int f4 = q * 512 + tid;         // 1024 float4 per 16x256 tile
            int r = f4 >> 6;
            int c = (f4 & 63) * 4;
            *(float4*)&Ls[r * 260 + c] = *(const float4*)&lsrc[r * 256 + c];
            *(float4*)&Ps[r * 260 + c] = *(const float4*)&psrc[r * 256 + c];
        }
        const float* a1src = g_A1 + (b * 256 + it) * 128;
        const float* b1src = g_B1 + (b * 256 + jt) * 128;
        {
            int f4 = tid;                    // 512 float4 per 16x128 tile
            int r = f4 >> 5;
            int c = (f4 & 31) * 4;
            *(float4*)&A1s[r * 132 + c] = *(const float4*)&a1src[r * 128 + c];
            *(float4*)&B1s[r * 132 + c] = *(const float4*)&b1src[r * 128 + c];
        }
        // W2 transposed into phase-2 region (disjoint from phase-1): W2s[h][g]=W2[g*128+h]
#pragma unroll
        for (int q = 0; q < 8; q++) {
            int f4 = q * 512 + tid;
            int f = f4 * 4;                  // = g*128 + h
            int g = f >> 7, h = f & 127;
            float4 v = *(const float4*)&W2[f];
            W2s[(h + 0) * 136 + g] = v.x;
            W2s[(h + 1) * 136 + g] = v.y;
            W2s[(h + 2) * 136 + g] = v.z;
            W2s[(h + 3) * 136 + g] = v.w;
        }
    }
    __syncthreads();

    float acc[8][8];
#pragma unroll
    for (int a = 0; a < 8; a++)
#pragma unroll
        for (int p = 0; p < 8; p++) acc[a][p] = 0.0f;

    const int xk = tid >> 4;   // Xs row this thread builds
    const int xi = tid & 15;   // i used for building

    for (int kc = 0; kc < 512; kc += 32) {
        // build Xs[xk][xi*16 + u]
        {
            int kk = kc + xk;
            if (kk < 256) {
                float lv = Ls[xi * 260 + kk];
#pragma unroll
                for (int u = 0; u < 16; u++)
                    Xs[xk * 256 + xi * 16 + u] = lv * Ps[u * 260 + kk];
            } else {
                int kd = kk - 256;
                float lv = Ls[xi * 260 + kd];
#pragma unroll
                for (int u = 0; u < 16; u++)
                    Xs[xk * 256 + xi * 16 + u] = fabsf(lv - Ps[u * 260 + kd]);
            }
        }
        // load Wks[k][h] = W1[h*1024 + 512 + kc + k]
        {
            int h = tid >> 2;
            int k0 = (tid & 3) * 8;
            const float* src = W1 + h * 1024 + 512 + kc + k0;
            float4 v0 = *(const float4*)(src);
            float4 v1 = *(const float4*)(src + 4);
            Wks[(k0 + 0) * 136 + h] = v0.x;
            Wks[(k0 + 1) * 136 + h] = v0.y;
            Wks[(k0 + 2) * 136 + h] = v0.z;
            Wks[(k0 + 3) * 136 + h] = v0.w;
            Wks[(k0 + 4) * 136 + h] = v1.x;
            Wks[(k0 + 5) * 136 + h] = v1.y;
            Wks[(k0 + 6) * 136 + h] = v1.z;
            Wks[(k0 + 7) * 136 + h] = v1.w;
        }
        __syncthreads();
#pragma unroll 4
        for (int k = 0; k < 32; k++) {
            float4 xa = *(const float4*)&Xs[k * 256 + p0];
            float4 xb = *(const float4*)&Xs[k * 256 + p0 + 4];
            float4 wa = *(const float4*)&Wks[k * 136 + h0];
            float4 wb = *(const float4*)&Wks[k * 136 + h0 + 4];
            float xv[8] = {xa.x, xa.y, xa.z, xa.w, xb.x, xb.y, xb.z, xb.w};
            float wv[8] = {wa.x, wa.y, wa.z, wa.w, wb.x, wb.y, wb.z, wb.w};
#pragma unroll
            for (int a = 0; a < 8; a++)
#pragma unroll
                for (int p = 0; p < 8; p++)
                    acc[a][p] += wv[a] * xv[p];
        }
        __syncthreads();
    }

    // epilogue1: + A1 + B1 (b1 folded into A1), gelu (in place)
#pragma unroll
    for (int a = 0; a < 8; a++) {
        float av = A1s[my_i * 132 + h0 + a];
#pragma unroll
        for (int p = 0; p < 8; p++) {
            float z = acc[a][p] + av + B1s[(j0 + p) * 132 + h0 + a];
            acc[a][p] = gelu_f(z);
        }
    }
    __syncthreads();   // phase-1 smem now dead; safe to write Yt
#pragma unroll
    for (int a = 0; a < 8; a++) {
#pragma unroll
        for (int p = 0; p < 8; p++)
            Yt[(h0 + a) * 264 + p0 + p] = acc[a][p];
    }
    __syncthreads();

    // GEMM2: out2[g][p] = sum_h Yt[h][p] * W2s[h][g]
#pragma unroll
    for (int a = 0; a < 8; a++)
#pragma unroll
        for (int p = 0; p < 8; p++) acc[a][p] = 0.0f;
#pragma unroll 4
    for (int h = 0; h < 128; h++) {
        float4 xa = *(const float4*)&Yt[h * 264 + p0];
        float4 xb = *(const float4*)&Yt[h * 264 + p0 + 4];
        float4 wa = *(const float4*)&W2s[h * 136 + h0];
        float4 wb = *(const float4*)&W2s[h * 136 + h0 + 4];
        float xv[8] = {xa.x, xa.y, xa.z, xa.w, xb.x, xb.y, xb.z, xb.w};
        float wv[8] = {wa.x, wa.y, wa.z, wa.w, wb.x, wb.y, wb.z, wb.w};
#pragma unroll
        for (int a = 0; a < 8; a++)
#pragma unroll
            for (int p = 0; p < 8; p++)
                acc[a][p] += wv[a] * xv[p];
    }

    // epilogue2: + b2, gelu, dot with w3 over this thread's 8 g's
    float part[8];
#pragma unroll
    for (int p = 0; p < 8; p++) part[p] = 0.0f;
#pragma unroll
    for (int gg = 0; gg < 8; gg++) {
        float w3v = W3[h0 + gg];
        float b2v = b2g[h0 + gg];
#pragma unroll
        for (int p = 0; p < 8; p++)
            part[p] += w3v * gelu_f(acc[gg][p] + b2v);
    }
    // reduce over the 16 hg lanes (xor offsets < 16 stay within each half-warp)
#pragma unroll
    for (int off = 8; off >= 1; off >>= 1) {
#pragma unroll
        for (int p = 0; p < 8; p++)
            part[p] += __shfl_xor_sync(0xFFFFFFFFu, part[p], off);
    }
    if (hg == 0) {
        const int gi = it + my_i;
        const int lpad = g_lmask[b * 256 + gi];
        const float b3v = b3[0];
#pragma unroll
        for (int p = 0; p < 8; p++) {
            int j = jt + j0 + p;
            float v = part[p] + b3v;
            if (isnan(v)) v = 0.0f;
            else if (isinf(v)) v = (v > 0.0f) ? 20.0f : -20.0f;
            if (lpad || g_pmask[b * 256 + j]) v = -20.0f;
            int idx = 4 + (b * 65536 + gi * 256 + j);
            out[idx] = v;
            out[idx + 262144] = 1.0f / (1.0f + expf(-v));
        }
    }
}

// ---------------------------------------------------------------------------
// Top-k (k=100) per batch: softmax-weighted sum is permutation invariant,
// so radix-select the 100th-largest key, then one exp-sum pass with ties.
// ---------------------------------------------------------------------------
__device__ __forceinline__ int wredsum_i(int v) {
#pragma unroll
    for (int o = 16; o; o >>= 1) v += __shfl_xor_sync(0xFFFFFFFFu, v, o);
    return v;
}
__device__ __forceinline__ float wredsum_f(float v) {
#pragma unroll
    for (int o = 16; o; o >>= 1) v += __shfl_xor_sync(0xFFFFFFFFu, v, o);
    return v;
}
__device__ __forceinline__ float wredmax_f(float v) {
#pragma unroll
    for (int o = 16; o; o >>= 1) v = fmaxf(v, __shfl_xor_sync(0xFFFFFFFFu, v, o));
    return v;
}

__global__ __launch_bounds__(1024) void topk_kernel(float* out) {
    const int b = blockIdx.x;
    const float* data = out + 4 + b * NPAIR_B;
    const int tid = threadIdx.x, lane = tid & 31, wid = tid >> 5;
    __shared__ float sf[32];
    __shared__ float sf2[32];
    __shared__ int si[32];
    __shared__ float s_M;
    __shared__ int s_tot;

    // global max
    float mx = -1e30f;
    for (int i = tid; i < NPAIR_B; i += 1024) mx = fmaxf(mx, data[i]);
    mx = wredmax_f(mx);
    if (lane == 0) sf[wid] = mx;
    __syncthreads();
    if (wid == 0) {
        float v = sf[lane];
        v = wredmax_f(v);
        if (lane == 0) s_M = v;
    }
    __syncthreads();
    const float M = s_M;

    // radix select of 100th-largest key
    unsigned prefix = 0u;
    for (int bit = 31; bit >= 0; --bit) {
        unsigned test = prefix | (1u << bit);
        int c = 0;
        for (int i = tid; i < NPAIR_B; i += 1024) {
            unsigned u = __float_as_uint(data[i]);
            unsigned k = (u & 0x80000000u) ? ~u : (u | 0x80000000u);
            c += (k >= test) ? 1 : 0;
        }
        c = wredsum_i(c);
        if (lane == 0) si[wid] = c;
        __syncthreads();
        if (wid == 0) {
            int v = si[lane];
            v = wredsum_i(v);
            if (lane == 0) s_tot = v;
        }
        __syncthreads();
        if (s_tot >= TOPK_K) prefix = test;
        __syncthreads();
    }

    // exp sums over strictly-greater values; include ties at threshold
    float s1 = 0.0f, s2 = 0.0f;
    int cg = 0;
    for (int i = tid; i < NPAIR_B; i += 1024) {
        float v = data[i];
        unsigned u = __float_as_uint(v);
        unsigned k = (u & 0x80000000u) ? ~u : (u | 0x80000000u);
        if (k > prefix) {
            float e = expf(v - M);
            s1 += e; s2 += e * v; cg++;
        }
    }
    s1 = wredsum_f(s1);
    s2 = wredsum_f(s2);
    cg = wredsum_i(cg);
    if (lane == 0) { sf[wid] = s1; sf2[wid] = s2; si[wid] = cg; }
    __syncthreads();
    if (tid == 0) {
        float S1 = 0.0f, S2 = 0.0f;
        int CG = 0;
        for (int w = 0; w < 32; w++) { S1 += sf[w]; S2 += sf2[w]; CG += si[w]; }
        unsigned u = (prefix & 0x80000000u) ? (prefix & 0x7FFFFFFFu) : ~prefix;
        float vT = __uint_as_float(u);
        int r = TOPK_K - CG;
        float e = expf(vT - M);
        S1 += (float)r * e;
        S2 += (float)r * e * vT;
        out[b] = S2 / S1;
    }
}

// ---------------------------------------------------------------------------
extern "C" void kernel_launch(void* const* d_in, const int* in_sizes, int n_in,
                              void* d_out, int out_size)
{
    const float* ltok = (const float*)d_in[0];
    const float* ptok = (const float*)d_in[1];
    const void*  lpad = d_in[2];
    const void*  ppad = d_in[3];
    const float* Wl = (const float*)d_in[4];
    const float* bl = (const float*)d_in[5];
    const float* Wp = (const float*)d_in[6];
    const float* bp = (const float*)d_in[7];
    const float* W1 = (const float*)d_in[8];
    const float* b1 = (const float*)d_in[9];
    const float* W2 = (const float*)d_in[10];
    const float* b2 = (const float*)d_in[11];
    const float* W3 = (const float*)d_in[12];
    const float* b3 = (const float*)d_in[13];
    float* out = (float*)d_out;

    detect_kernel<<<2, 256>>>((const unsigned char*)lpad, (const unsigned char*)ppad);
    mask_kernel<<<2, 1024>>>(lpad, ppad);
    proj_kernel<<<dim3(4, 32), 256>>>(ltok, ptok, Wl, bl, Wp, bp);
    a1b1_kernel<<<dim3(2, 32), 256>>>(W1, b1);

    cudaFuncSetAttribute(pair_kernel, cudaFuncAttributeMaxDynamicSharedMemorySize, 204800);
    pair_kernel<<<dim3(16, 16, 4), 512, 204800>>>(W1, W2, W3, b2, b3, out);

    topk_kernel<<<4, 1024>>>(out);
}